// round 16
// baseline (speedup 1.0000x reference)
#include <cuda_runtime.h>
#include <math.h>

// Problem dims (fixed by dataset)
#define NMAX   50000
#define EMAX   400000
#define E0MAX  200000
#define INCH   128
#define HID    32
#define FD     3
#define FDH    96
#define OUTCH  32

// ---------------- scratch (static device globals) ----------------
__device__ float  g_x   [NMAX * FDH];
__device__ float  g_y   [NMAX * FDH];
__device__ float4 g_proj[NMAX];         // {sheaf_row, sheaf_col, wt_row, wt_col}
__device__ float4 g_ec  [EMAX];         // per-CSR-slot {t00, t01s, w2, col_bits}
__device__ float  g_degA[NMAX];
__device__ float  g_degB[NMAX];
__device__ int    g_cnt [NMAX];
__device__ int    g_ofs [NMAX];
__device__ int    g_num [NMAX];
__device__ int    g_pos [EMAX];         // directed edge -> CSR slot
__device__ int    g_total;
__device__ float  g_W1t [INCH * FDH];   // [k][j]
__device__ float  g_W2t [FDH * OUTCH];  // [k][o]
__device__ float  g_Wl  [2 * 9];
__device__ float  g_WrT [2 * HID * HID];// [h][c]
__device__ float  g_coeff[2 * FD];

__device__ __forceinline__ float warp_sum(float v) {
    #pragma unroll
    for (int o = 16; o > 0; o >>= 1) v += __shfl_xor_sync(0xffffffffu, v, o);
    return v;
}
__device__ __forceinline__ float elu1(float t) { return t > 0.0f ? t : expm1f(t); }

// ---------------- init: zero counters + transpose W1, W2 ----------------
__global__ void k_init(const float* __restrict__ W1, const float* __restrict__ W2, int N) {
    int i = blockIdx.x * blockDim.x + threadIdx.x;
    if (i == 0) g_total = 0;
    if (i < N) g_cnt[i] = 0;
    if (i < INCH * FDH) {
        int j = i / INCH, k = i % INCH;
        g_W1t[k * FDH + j] = W1[i];
    } else if (i < INCH * FDH + FDH * OUTCH) {
        int t = i - INCH * FDH;
        int o = t / FDH, k = t % FDH;
        g_W2t[k * OUTCH + o] = W2[t];
    }
}

// ---------------- merged: spectral norm (blocks 0,1) || histogram (rest) ----------------
__global__ void k_spec_hist(const float* __restrict__ Wl_in,
                            const float* __restrict__ Wr_in,
                            const float* __restrict__ eps_in,
                            const int* __restrict__ row, int E) {
    if (blockIdx.x >= 2) {
        int i = ((blockIdx.x - 2) * blockDim.x + threadIdx.x) * 4;
        if (i + 3 < E) {
            int4 r = *(const int4*)(row + i);
            atomicAdd(&g_cnt[r.x], 1);
            atomicAdd(&g_cnt[r.y], 1);
            atomicAdd(&g_cnt[r.z], 1);
            atomicAdd(&g_cnt[r.w], 1);
        } else {
            for (int j = i; j < E; j++) atomicAdd(&g_cnt[row[j]], 1);
        }
        return;
    }
    if (threadIdx.x >= 32) return;

    int layer = blockIdx.x;
    const float* wl = Wl_in + layer * 9;
    const float* wr = Wr_in + layer * HID * HID;
    const float* ep = eps_in + layer * 3;

    __shared__ float W[HID * HID];
    __shared__ float u[HID], v[HID];
    int t = threadIdx.x;

    for (int i = t; i < HID * HID; i += 32) W[i] = wr[i];
    u[t] = 0.1767766953f;
    __syncwarp();
    for (int it = 0; it < 20; it++) {
        float vj = 0.0f;
        #pragma unroll 8
        for (int i = 0; i < HID; i++) vj = fmaf(W[i * HID + t], u[i], vj);
        float nv = sqrtf(warp_sum(vj * vj)) + 1e-12f;
        v[t] = vj / nv;
        __syncwarp();
        float ui = 0.0f;
        #pragma unroll 8
        for (int j = 0; j < HID; j++) ui = fmaf(W[t * HID + j], v[j], ui);
        float nu = sqrtf(warp_sum(ui * ui)) + 1e-12f;
        u[t] = ui / nu;
        __syncwarp();
    }
    {
        float vj = 0.0f;
        #pragma unroll 8
        for (int i = 0; i < HID; i++) vj = fmaf(W[i * HID + t], u[i], vj);
        float nv = sqrtf(warp_sum(vj * vj)) + 1e-12f;
        v[t] = vj / nv;
        __syncwarp();
    }
    float wi = 0.0f;
    #pragma unroll 8
    for (int j = 0; j < HID; j++) wi = fmaf(W[t * HID + j], v[j], wi);
    float sigma = warp_sum(u[t] * wi);
    float inv = 1.0f / sigma;
    for (int i = t; i < HID * HID; i += 32) {
        int c = i >> 5, h = i & 31;
        g_WrT[layer * HID * HID + h * HID + c] = W[c * HID + h] * inv;
    }
    if (t == 0) {
        float Wl[9], ul[3], vl[3];
        #pragma unroll
        for (int i = 0; i < 9; i++) Wl[i] = wl[i];
        ul[0] = ul[1] = ul[2] = 0.57735026919f;
        for (int it = 0; it < 20; it++) {
            #pragma unroll
            for (int j = 0; j < 3; j++)
                vl[j] = Wl[j] * ul[0] + Wl[3 + j] * ul[1] + Wl[6 + j] * ul[2];
            float nv = sqrtf(vl[0]*vl[0] + vl[1]*vl[1] + vl[2]*vl[2]) + 1e-12f;
            vl[0] /= nv; vl[1] /= nv; vl[2] /= nv;
            #pragma unroll
            for (int i = 0; i < 3; i++)
                ul[i] = Wl[i*3] * vl[0] + Wl[i*3+1] * vl[1] + Wl[i*3+2] * vl[2];
            float nu = sqrtf(ul[0]*ul[0] + ul[1]*ul[1] + ul[2]*ul[2]) + 1e-12f;
            ul[0] /= nu; ul[1] /= nu; ul[2] /= nu;
        }
        #pragma unroll
        for (int j = 0; j < 3; j++)
            vl[j] = Wl[j] * ul[0] + Wl[3 + j] * ul[1] + Wl[6 + j] * ul[2];
        float nv = sqrtf(vl[0]*vl[0] + vl[1]*vl[1] + vl[2]*vl[2]) + 1e-12f;
        vl[0] /= nv; vl[1] /= nv; vl[2] /= nv;
        float sig = 0.0f;
        #pragma unroll
        for (int i = 0; i < 3; i++)
            sig += ul[i] * (Wl[i*3] * vl[0] + Wl[i*3+1] * vl[1] + Wl[i*3+2] * vl[2]);
        float invl = 1.0f / sig;
        #pragma unroll
        for (int i = 0; i < 9; i++) g_Wl[layer * 9 + i] = Wl[i] * invl;
        #pragma unroll
        for (int f = 0; f < 3; f++) g_coeff[layer * 3 + f] = 1.0f + tanhf(ep[f]);
    }
}

__global__ void k_assign(int N) {
    int n = blockIdx.x * blockDim.x + threadIdx.x;
    if (n >= N) return;
    int c = g_cnt[n];
    int pos = atomicAdd(&g_total, c);
    g_ofs[n] = pos;
    g_num[n] = c;
    g_cnt[n] = pos;
}

// ---------------- proj helper ----------------
__device__ __forceinline__ void do_proj(int n, int lane, float h0, float h1, float h2,
                                        const float* __restrict__ ws,
                                        const float* __restrict__ wt) {
    float sr = h0 * ws[lane]      + h1 * ws[32 + lane]  + h2 * ws[64 + lane];
    float sc = h0 * ws[96 + lane] + h1 * ws[128 + lane] + h2 * ws[160 + lane];
    float wr = h0 * wt[lane]      + h1 * wt[32 + lane]  + h2 * wt[64 + lane];
    float wc = h0 * wt[96 + lane] + h1 * wt[128 + lane] + h2 * wt[160 + lane];
    sr = warp_sum(sr); sc = warp_sum(sc); wr = warp_sum(wr); wc = warp_sum(wc);
    if (lane == 0) g_proj[n] = make_float4(sr, sc, wr, wc);
}

// ---------------- K0: lin1 tiled GEMM (blocks < nb64)  ||  CSR scatter (rest) ----------------
__global__ void __launch_bounds__(256) k_lin1S(const float* __restrict__ x,
                                               const float* __restrict__ b1,
                                               const float* __restrict__ ws,
                                               const float* __restrict__ wt,
                                               const int* __restrict__ row,
                                               int N, int E, int nb64) {
    if ((int)blockIdx.x >= nb64) {
        // ---- scatter part: record inverse map edge -> CSR slot ----
        int e = ((int)blockIdx.x - nb64) * (int)blockDim.x + (int)threadIdx.x;
        if (e < E) {
            int pos = atomicAdd(&g_cnt[row[e]], 1);
            g_pos[e] = pos;
        }
        return;
    }

    __shared__ float SM[64 * 97];
    __shared__ float sWgt[4 * 96];
    float* XS = SM;
    float* WS = SM + 64 * 33;
    float* PS = SM;

    int tid = threadIdx.x;
    int tm = tid & 31, tn = tid >> 5;
    int n0 = blockIdx.x * 64;
    int nn = min(64, N - n0);

    int r0 = tid >> 3, q0 = tid & 7;
    int r1 = (tid + 256) >> 3;
    const float* xp0 = x + (size_t)(n0 + ((r0 < nn) ? r0 : 0)) * INCH + q0 * 4;
    const float* xp1 = x + (size_t)(n0 + ((r1 < nn) ? r1 : 0)) * INCH + q0 * 4;
    float4 xr0[4], xr1[4];
    #pragma unroll
    for (int kt = 0; kt < 4; kt++) xr0[kt] = *(const float4*)(xp0 + kt * 32);
    #pragma unroll
    for (int kt = 0; kt < 4; kt++) xr1[kt] = *(const float4*)(xp1 + kt * 32);

    for (int i = tid; i < 192; i += 256) { sWgt[i] = ws[i]; sWgt[192 + i] = wt[i]; }

    float acc0[12], acc1[12];
    #pragma unroll
    for (int c = 0; c < 12; c++) { float b = b1[tn * 12 + c]; acc0[c] = b; acc1[c] = b; }

    #pragma unroll
    for (int kt = 0; kt < 4; kt++) {
        {
            float* d0 = &XS[r0 * 33 + q0 * 4];
            d0[0] = xr0[kt].x; d0[1] = xr0[kt].y; d0[2] = xr0[kt].z; d0[3] = xr0[kt].w;
            float* d1 = &XS[r1 * 33 + q0 * 4];
            d1[0] = xr1[kt].x; d1[1] = xr1[kt].y; d1[2] = xr1[kt].z; d1[3] = xr1[kt].w;
        }
        for (int l = tid; l < 768; l += 256) {
            int r = l / 24, q = l % 24;
            float4 v = *(const float4*)(g_W1t + (size_t)(kt * 32 + r) * FDH + q * 4);
            float* d = &WS[r * 96 + q * 4];
            d[0] = v.x; d[1] = v.y; d[2] = v.z; d[3] = v.w;
        }
        __syncthreads();
        #pragma unroll 4
        for (int k = 0; k < 32; k++) {
            float a0 = XS[tm * 33 + k];
            float a1 = XS[(tm + 32) * 33 + k];
            const float* wk = &WS[k * 96 + tn * 12];
            float4 b0 = *(const float4*)(wk);
            float4 b1v = *(const float4*)(wk + 4);
            float4 b2 = *(const float4*)(wk + 8);
            acc0[0] = fmaf(a0, b0.x, acc0[0]);  acc1[0] = fmaf(a1, b0.x, acc1[0]);
            acc0[1] = fmaf(a0, b0.y, acc0[1]);  acc1[1] = fmaf(a1, b0.y, acc1[1]);
            acc0[2] = fmaf(a0, b0.z, acc0[2]);  acc1[2] = fmaf(a1, b0.z, acc1[2]);
            acc0[3] = fmaf(a0, b0.w, acc0[3]);  acc1[3] = fmaf(a1, b0.w, acc1[3]);
            acc0[4] = fmaf(a0, b1v.x, acc0[4]); acc1[4] = fmaf(a1, b1v.x, acc1[4]);
            acc0[5] = fmaf(a0, b1v.y, acc0[5]); acc1[5] = fmaf(a1, b1v.y, acc1[5]);
            acc0[6] = fmaf(a0, b1v.z, acc0[6]); acc1[6] = fmaf(a1, b1v.z, acc1[6]);
            acc0[7] = fmaf(a0, b1v.w, acc0[7]); acc1[7] = fmaf(a1, b1v.w, acc1[7]);
            acc0[8] = fmaf(a0, b2.x, acc0[8]);  acc1[8] = fmaf(a1, b2.x, acc1[8]);
            acc0[9] = fmaf(a0, b2.y, acc0[9]);  acc1[9] = fmaf(a1, b2.y, acc1[9]);
            acc0[10] = fmaf(a0, b2.z, acc0[10]); acc1[10] = fmaf(a1, b2.z, acc1[10]);
            acc0[11] = fmaf(a0, b2.w, acc0[11]); acc1[11] = fmaf(a1, b2.w, acc1[11]);
        }
        __syncthreads();
    }

    #pragma unroll
    for (int c = 0; c < 12; c++) { acc0[c] = elu1(acc0[c]); acc1[c] = elu1(acc1[c]); }
    if (tm < nn) {
        float* xo = g_x + (size_t)(n0 + tm) * FDH + tn * 12;
        #pragma unroll
        for (int q = 0; q < 3; q++)
            *(float4*)(xo + q * 4) = make_float4(acc0[q*4], acc0[q*4+1], acc0[q*4+2], acc0[q*4+3]);
    }
    if (tm + 32 < nn) {
        float* xo = g_x + (size_t)(n0 + tm + 32) * FDH + tn * 12;
        #pragma unroll
        for (int q = 0; q < 3; q++)
            *(float4*)(xo + q * 4) = make_float4(acc1[q*4], acc1[q*4+1], acc1[q*4+2], acc1[q*4+3]);
    }
    {
        float* p0 = &PS[tm * 97 + tn * 12];
        float* p1 = &PS[(tm + 32) * 97 + tn * 12];
        #pragma unroll
        for (int c = 0; c < 12; c++) { p0[c] = acc0[c]; p1[c] = acc1[c]; }
    }
    __syncthreads();

    {
        int node = tid & 63;
        int widx = tid >> 6;
        if (node < nn) {
            const float* pv = &PS[node * 97];
            const float* wv = &sWgt[widx * 96];
            float s = 0.0f;
            #pragma unroll 8
            for (int j = 0; j < 96; j++) s = fmaf(pv[j], wv[j], s);
            ((float*)&g_proj[n0 + node])[widx] = s;
        }
        if (tid < nn) { g_degA[n0 + tid] = 0.0f; g_degB[n0 + tid] = 0.0f; }
    }
}

// ---------------- merged: edge transport+degree (CSR-slot writes)  ||  y-GEMM ----------------
__global__ void __launch_bounds__(256) k_edge_y(const int* __restrict__ row,
                                                const int* __restrict__ col,
                                                int layer, int E0, int nbE, int N) {
    if ((int)blockIdx.x < nbE) {
        int e = blockIdx.x * blockDim.x + threadIdx.x;
        if (e >= E0) return;
        float* deg = (layer == 0) ? g_degA : g_degB;
        int r = row[e], c = col[e];
        int pf = g_pos[e], pb = g_pos[e + E0];
        float4 pr = g_proj[r], pc = g_proj[c];
        float af = tanhf(pr.x + pc.y);
        float ab = tanhf(pc.x + pr.y);
        float af2 = af * af, ab2 = ab * ab;
        float invf = 1.0f / (1.0f + af2), invb = 1.0f / (1.0f + ab2);
        float cf = (1.0f - af2) * invf, sf = 2.0f * af * invf;
        float cb = (1.0f - ab2) * invb, sb = 2.0f * ab * invb;
        float t00 = cf * cb + sf * sb;
        float t01 = sf * cb - cf * sb;
        float wf = 1.0f / (1.0f + expf(-(pr.z + pc.w)));
        float wb = 1.0f / (1.0f + expf(-(pc.z + pr.w)));
        float w = wf * wb, w2 = w * w;
        g_ec[pf] = make_float4(t00,  t01, w2, __int_as_float(c));
        g_ec[pb] = make_float4(t00, -t01, w2, __int_as_float(r));
        atomicAdd(&deg[r], w2);
        atomicAdd(&deg[c], w2);
        return;
    }

    __shared__ float MS[192 * 33];
    __shared__ float sB[HID * HID];
    __shared__ float sWl[9];
    int tid = threadIdx.x;
    for (int i = tid; i < HID * HID; i += 256) sB[i] = g_WrT[layer * HID * HID + i];
    if (tid < 9) sWl[tid] = g_Wl[layer * 9 + tid];
    __syncthreads();

    int n0 = ((int)blockIdx.x - nbE) * 64;
    int nn = min(64, N - n0);
    if (nn <= 0) return;
    int tot = nn * FDH;
    for (int idx = tid; idx < tot; idx += 256) {
        int m = idx >> 5, h = idx & 31;
        int nl = m / 3, f = m % 3;
        const float* xr = g_x + (size_t)(n0 + nl) * FDH + h;
        MS[m * 33 + h] = sWl[f * 3 + 0] * xr[0] + sWl[f * 3 + 1] * xr[32]
                       + sWl[f * 3 + 2] * xr[64];
    }
    __syncthreads();

    int tm = tid & 31, tn = tid >> 5;
    float acc[6][4];
    #pragma unroll
    for (int j = 0; j < 6; j++)
        #pragma unroll
        for (int q = 0; q < 4; q++) acc[j][q] = 0.0f;

    #pragma unroll 4
    for (int k = 0; k < HID; k++) {
        float4 bv = *(const float4*)&sB[k * HID + tn * 4];
        #pragma unroll
        for (int j = 0; j < 6; j++) {
            float a = MS[(tm + j * 32) * 33 + k];
            acc[j][0] = fmaf(a, bv.x, acc[j][0]);
            acc[j][1] = fmaf(a, bv.y, acc[j][1]);
            acc[j][2] = fmaf(a, bv.z, acc[j][2]);
            acc[j][3] = fmaf(a, bv.w, acc[j][3]);
        }
    }
    #pragma unroll
    for (int j = 0; j < 6; j++) {
        int m = tm + j * 32;
        int nl = m / 3, f = m % 3;
        if (nl < nn) {
            float4* yo = (float4*)(g_y + (size_t)(n0 + nl) * FDH + f * 32 + tn * 4);
            *yo = make_float4(acc[j][0], acc[j][1], acc[j][2], acc[j][3]);
        }
    }
}

// ---------------- gather: agg + update x; warp per node; 4-deep pipeline ----------------
#define GACC(EC, Y0, Y1, Y2, DC)                                     \
    { float ic = ((DC) > 0.0f) ? rsqrtf(fmaxf((DC), 1e-30f)) : 0.0f; \
      float cc = (EC).z * ir * ic;                                   \
      A0 = fmaf(cc, fmaf((EC).x, (Y0),  (EC).y * (Y1)), A0);         \
      A1 = fmaf(cc, fmaf((EC).x, (Y1), -(EC).y * (Y0)), A1);         \
      A2 = fmaf(cc, (Y2), A2); }
#define GLOAD(EC, Y0, Y1, Y2, DC, IDX)                               \
    { (EC) = ep[IDX];                                                \
      int ci_ = __float_as_int((EC).w);                              \
      const float* yc = g_y + (size_t)ci_ * FDH;                     \
      (Y0) = yc[lane]; (Y1) = yc[32 + lane]; (Y2) = yc[64 + lane];   \
      (DC) = deg[ci_]; }

__global__ void __launch_bounds__(256) k_gather(int layer,
                                                const float* __restrict__ ws,
                                                const float* __restrict__ wt, int N) {
    int tid  = threadIdx.x;
    int n    = (blockIdx.x * blockDim.x + tid) >> 5;
    int lane = tid & 31;
    if (n >= N) return;
    const float* deg = (layer == 0) ? g_degA : g_degB;
    const float* coeff = g_coeff + layer * 3;

    float dn = deg[n];
    float diag = (dn > 0.0f) ? 1.0f : 0.0f;
    float ir = (dn > 0.0f) ? rsqrtf(fmaxf(dn, 1e-30f)) : 0.0f;
    int beg = g_ofs[n], cnt = g_num[n];
    const float4* ep = g_ec + beg;
    float A0 = 0.0f, A1 = 0.0f, A2 = 0.0f;

    float4 e0, e1, e2, e3;
    float y00, y01, y02, y10, y11, y12, y20, y21, y22, y30, y31, y32;
    float d0, d1, d2, d3;
    if (cnt > 0) GLOAD(e0, y00, y01, y02, d0, 0);
    if (cnt > 1) GLOAD(e1, y10, y11, y12, d1, 1);
    if (cnt > 2) GLOAD(e2, y20, y21, y22, d2, 2);
    if (cnt > 3) GLOAD(e3, y30, y31, y32, d3, 3);

    int i = 0;
    while (i + 4 <= cnt) {
        GACC(e0, y00, y01, y02, d0); if (i + 4 < cnt) GLOAD(e0, y00, y01, y02, d0, i + 4);
        GACC(e1, y10, y11, y12, d1); if (i + 5 < cnt) GLOAD(e1, y10, y11, y12, d1, i + 5);
        GACC(e2, y20, y21, y22, d2); if (i + 6 < cnt) GLOAD(e2, y20, y21, y22, d2, i + 6);
        GACC(e3, y30, y31, y32, d3); if (i + 7 < cnt) GLOAD(e3, y30, y31, y32, d3, i + 7);
        i += 4;
    }
    int rem = cnt - i;
    if (rem > 0) GACC(e0, y00, y01, y02, d0);
    if (rem > 1) GACC(e1, y10, y11, y12, d1);
    if (rem > 2) GACC(e2, y20, y21, y22, d2);

    const float* yn = g_y + (size_t)n * FDH;
    float* xr = g_x + (size_t)n * FDH;
    float x0 = coeff[0] * xr[lane]      - elu1(diag * yn[lane]      - A0);
    float x1 = coeff[1] * xr[32 + lane] - elu1(diag * yn[32 + lane] - A1);
    float x2 = coeff[2] * xr[64 + lane] - elu1(diag * yn[64 + lane] - A2);
    xr[lane] = x0; xr[32 + lane] = x1; xr[64 + lane] = x2;
    if (layer == 0) do_proj(n, lane, x0, x1, x2, ws, wt);
}

// ---------------- out: final GEMM x[N,96] @ W2t[96,32] + b2; 64 nodes/block ----------------
__global__ void __launch_bounds__(256) k_out(const float* __restrict__ b2,
                                             float* __restrict__ out, int N) {
    __shared__ float XS[64 * 97];
    __shared__ float sB[FDH * OUTCH];
    int tid = threadIdx.x;
    for (int i = tid; i < FDH * OUTCH; i += 256) sB[i] = g_W2t[i];

    int n0 = blockIdx.x * 64;
    int nn = min(64, N - n0);
    for (int idx = tid; idx < nn * 24; idx += 256) {
        int nl = idx / 24, q = idx % 24;
        float4 v = *(const float4*)(g_x + (size_t)(n0 + nl) * FDH + q * 4);
        float* d = &XS[nl * 97 + q * 4];
        d[0] = v.x; d[1] = v.y; d[2] = v.z; d[3] = v.w;
    }
    __syncthreads();

    int tm = tid & 31, tn = tid >> 5;
    float4 bias = *(const float4*)(b2 + tn * 4);
    float acc0[4] = {bias.x, bias.y, bias.z, bias.w};
    float acc1[4] = {bias.x, bias.y, bias.z, bias.w};
    #pragma unroll 4
    for (int k = 0; k < FDH; k++) {
        float4 bv = *(const float4*)&sB[k * OUTCH + tn * 4];
        float a0 = XS[tm * 97 + k];
        float a1 = XS[(tm + 32) * 97 + k];
        acc0[0] = fmaf(a0, bv.x, acc0[0]); acc0[1] = fmaf(a0, bv.y, acc0[1]);
        acc0[2] = fmaf(a0, bv.z, acc0[2]); acc0[3] = fmaf(a0, bv.w, acc0[3]);
        acc1[0] = fmaf(a1, bv.x, acc1[0]); acc1[1] = fmaf(a1, bv.y, acc1[1]);
        acc1[2] = fmaf(a1, bv.z, acc1[2]); acc1[3] = fmaf(a1, bv.w, acc1[3]);
    }
    if (tm < nn)
        *(float4*)(out + (size_t)(n0 + tm) * OUTCH + tn * 4) =
            make_float4(acc0[0], acc0[1], acc0[2], acc0[3]);
    if (tm + 32 < nn)
        *(float4*)(out + (size_t)(n0 + tm + 32) * OUTCH + tn * 4) =
            make_float4(acc1[0], acc1[1], acc1[2], acc1[3]);
}

// ---------------- launch ----------------
extern "C" void kernel_launch(void* const* d_in, const int* in_sizes, int n_in,
                              void* d_out, int out_size)
{
    const float* x      = (const float*)d_in[0];
    const int*   ei     = (const int*)  d_in[1];
    const float* W1     = (const float*)d_in[2];
    const float* b1     = (const float*)d_in[3];
    const float* W2     = (const float*)d_in[4];
    const float* b2     = (const float*)d_in[5];
    const float* Wleft  = (const float*)d_in[6];
    const float* Wright = (const float*)d_in[7];
    const float* eps    = (const float*)d_in[8];
    const float* Wsheaf = (const float*)d_in[9];
    const float* Wwt    = (const float*)d_in[10];
    float* out = (float*)d_out;

    int N  = in_sizes[0] / INCH;
    int E  = in_sizes[1] / 2;
    int E0 = E / 2;
    const int* row = ei;
    const int* col = ei + E;

    int nbE  = (E0 + 255) / 256;
    int nb64 = (N + 63) / 64;
    int nbH  = (E / 4 + 255) / 256;
    int nbS  = (E + 255) / 256;

    k_init<<<(N + 255) / 256, 256>>>(W1, W2, N);                       // 1
    k_spec_hist<<<2 + nbH, 256>>>(Wleft, Wright, eps, row, E);         // 2
    k_assign<<<(N + 255) / 256, 256>>>(N);                             // 3
    k_lin1S<<<nb64 + nbS, 256>>>(x, b1, Wsheaf + 192, Wwt, row, N, E, nb64); // 4 <- profiled
    // layer 0
    k_edge_y<<<nbE + nb64, 256>>>(row, col, 0, E0, nbE, N);            // 5
    k_gather<<<(N * 32 + 255) / 256, 256>>>(0, Wsheaf + 576 + 192, Wwt + 192, N); // 6
    // layer 1
    k_edge_y<<<nbE + nb64, 256>>>(row, col, 1, E0, nbE, N);            // 7
    k_gather<<<(N * 32 + 255) / 256, 256>>>(1, Wsheaf, Wwt, N);        // 8

    k_out<<<nb64, 256>>>(b2, out, N);                                  // 9
}

// round 17
// speedup vs baseline: 1.5070x; 1.5070x over previous
#include <cuda_runtime.h>
#include <math.h>

// Problem dims (fixed by dataset)
#define NMAX   50000
#define EMAX   400000
#define E0MAX  200000
#define INCH   128
#define HID    32
#define FD     3
#define FDH    96
#define OUTCH  32

// ---------------- scratch (static device globals) ----------------
__device__ float  g_x   [NMAX * FDH];
__device__ float  g_y   [NMAX * FDH];
__device__ float4 g_proj[NMAX];         // {sheaf_row, sheaf_col, wt_row, wt_col}
__device__ float4 g_ec  [EMAX];         // per-CSR-slot {t00, t01s, w2, col_bits}
__device__ float  g_degA[NMAX];
__device__ float  g_degB[NMAX];
__device__ int    g_cnt [NMAX];
__device__ int    g_ofs [NMAX];
__device__ int    g_num [NMAX];
__device__ int    g_pos [EMAX];         // directed edge -> CSR slot
__device__ int    g_total;
__device__ float  g_W1t [INCH * FDH];   // [k][j]
__device__ float  g_W2t [FDH * OUTCH];  // [k][o]
__device__ float  g_Wl  [2 * 9];
__device__ float  g_WrT [2 * HID * HID];// [h][c]
__device__ float  g_coeff[2 * FD];

__device__ __forceinline__ float warp_sum(float v) {
    #pragma unroll
    for (int o = 16; o > 0; o >>= 1) v += __shfl_xor_sync(0xffffffffu, v, o);
    return v;
}
__device__ __forceinline__ float elu1(float t) { return t > 0.0f ? t : expm1f(t); }

// ---------------- init: zero counters + transpose W1, W2 ----------------
__global__ void k_init(const float* __restrict__ W1, const float* __restrict__ W2, int N) {
    int i = blockIdx.x * blockDim.x + threadIdx.x;
    if (i == 0) g_total = 0;
    if (i < N) g_cnt[i] = 0;
    if (i < INCH * FDH) {
        int j = i / INCH, k = i % INCH;
        g_W1t[k * FDH + j] = W1[i];
    } else if (i < INCH * FDH + FDH * OUTCH) {
        int t = i - INCH * FDH;
        int o = t / FDH, k = t % FDH;
        g_W2t[k * OUTCH + o] = W2[t];
    }
}

// ---------------- merged: spectral norm (blocks 0,1) || histogram (rest) ----------------
__global__ void k_spec_hist(const float* __restrict__ Wl_in,
                            const float* __restrict__ Wr_in,
                            const float* __restrict__ eps_in,
                            const int* __restrict__ row, int E) {
    if (blockIdx.x >= 2) {
        int i = ((blockIdx.x - 2) * blockDim.x + threadIdx.x) * 4;
        if (i + 3 < E) {
            int4 r = *(const int4*)(row + i);
            atomicAdd(&g_cnt[r.x], 1);
            atomicAdd(&g_cnt[r.y], 1);
            atomicAdd(&g_cnt[r.z], 1);
            atomicAdd(&g_cnt[r.w], 1);
        } else {
            for (int j = i; j < E; j++) atomicAdd(&g_cnt[row[j]], 1);
        }
        return;
    }
    if (threadIdx.x >= 32) return;

    int layer = blockIdx.x;
    const float* wl = Wl_in + layer * 9;
    const float* wr = Wr_in + layer * HID * HID;
    const float* ep = eps_in + layer * 3;

    __shared__ float W[HID * HID];
    __shared__ float u[HID], v[HID];
    int t = threadIdx.x;

    for (int i = t; i < HID * HID; i += 32) W[i] = wr[i];
    u[t] = 0.1767766953f;
    __syncwarp();
    for (int it = 0; it < 20; it++) {
        float vj = 0.0f;
        #pragma unroll 8
        for (int i = 0; i < HID; i++) vj = fmaf(W[i * HID + t], u[i], vj);
        float nv = sqrtf(warp_sum(vj * vj)) + 1e-12f;
        v[t] = vj / nv;
        __syncwarp();
        float ui = 0.0f;
        #pragma unroll 8
        for (int j = 0; j < HID; j++) ui = fmaf(W[t * HID + j], v[j], ui);
        float nu = sqrtf(warp_sum(ui * ui)) + 1e-12f;
        u[t] = ui / nu;
        __syncwarp();
    }
    {
        float vj = 0.0f;
        #pragma unroll 8
        for (int i = 0; i < HID; i++) vj = fmaf(W[i * HID + t], u[i], vj);
        float nv = sqrtf(warp_sum(vj * vj)) + 1e-12f;
        v[t] = vj / nv;
        __syncwarp();
    }
    float wi = 0.0f;
    #pragma unroll 8
    for (int j = 0; j < HID; j++) wi = fmaf(W[t * HID + j], v[j], wi);
    float sigma = warp_sum(u[t] * wi);
    float inv = 1.0f / sigma;
    for (int i = t; i < HID * HID; i += 32) {
        int c = i >> 5, h = i & 31;
        g_WrT[layer * HID * HID + h * HID + c] = W[c * HID + h] * inv;
    }
    if (t == 0) {
        float Wl[9], ul[3], vl[3];
        #pragma unroll
        for (int i = 0; i < 9; i++) Wl[i] = wl[i];
        ul[0] = ul[1] = ul[2] = 0.57735026919f;
        for (int it = 0; it < 20; it++) {
            #pragma unroll
            for (int j = 0; j < 3; j++)
                vl[j] = Wl[j] * ul[0] + Wl[3 + j] * ul[1] + Wl[6 + j] * ul[2];
            float nv = sqrtf(vl[0]*vl[0] + vl[1]*vl[1] + vl[2]*vl[2]) + 1e-12f;
            vl[0] /= nv; vl[1] /= nv; vl[2] /= nv;
            #pragma unroll
            for (int i = 0; i < 3; i++)
                ul[i] = Wl[i*3] * vl[0] + Wl[i*3+1] * vl[1] + Wl[i*3+2] * vl[2];
            float nu = sqrtf(ul[0]*ul[0] + ul[1]*ul[1] + ul[2]*ul[2]) + 1e-12f;
            ul[0] /= nu; ul[1] /= nu; ul[2] /= nu;
        }
        #pragma unroll
        for (int j = 0; j < 3; j++)
            vl[j] = Wl[j] * ul[0] + Wl[3 + j] * ul[1] + Wl[6 + j] * ul[2];
        float nv = sqrtf(vl[0]*vl[0] + vl[1]*vl[1] + vl[2]*vl[2]) + 1e-12f;
        vl[0] /= nv; vl[1] /= nv; vl[2] /= nv;
        float sig = 0.0f;
        #pragma unroll
        for (int i = 0; i < 3; i++)
            sig += ul[i] * (Wl[i*3] * vl[0] + Wl[i*3+1] * vl[1] + Wl[i*3+2] * vl[2]);
        float invl = 1.0f / sig;
        #pragma unroll
        for (int i = 0; i < 9; i++) g_Wl[layer * 9 + i] = Wl[i] * invl;
        #pragma unroll
        for (int f = 0; f < 3; f++) g_coeff[layer * 3 + f] = 1.0f + tanhf(ep[f]);
    }
}

__global__ void k_assign(int N) {
    int n = blockIdx.x * blockDim.x + threadIdx.x;
    if (n >= N) return;
    int c = g_cnt[n];
    int pos = atomicAdd(&g_total, c);
    g_ofs[n] = pos;
    g_num[n] = c;
    g_cnt[n] = pos;
}
// scatter: record inverse map edge -> CSR slot
__global__ void k_scatter(const int* __restrict__ row, int E) {
    int e = blockIdx.x * blockDim.x + threadIdx.x;
    if (e >= E) return;
    int pos = atomicAdd(&g_cnt[row[e]], 1);
    g_pos[e] = pos;
}

// ---------------- proj helper ----------------
__device__ __forceinline__ void do_proj(int n, int lane, float h0, float h1, float h2,
                                        const float* __restrict__ ws,
                                        const float* __restrict__ wt) {
    float sr = h0 * ws[lane]      + h1 * ws[32 + lane]  + h2 * ws[64 + lane];
    float sc = h0 * ws[96 + lane] + h1 * ws[128 + lane] + h2 * ws[160 + lane];
    float wr = h0 * wt[lane]      + h1 * wt[32 + lane]  + h2 * wt[64 + lane];
    float wc = h0 * wt[96 + lane] + h1 * wt[128 + lane] + h2 * wt[160 + lane];
    sr = warp_sum(sr); sc = warp_sum(sc); wr = warp_sum(wr); wc = warp_sum(wc);
    if (lane == 0) g_proj[n] = make_float4(sr, sc, wr, wc);
}

// ---------------- K0: lin1 as smem-tiled GEMM, front-batched x loads ----------------
__global__ void __launch_bounds__(256) k_lin1G(const float* __restrict__ x,
                                               const float* __restrict__ b1,
                                               const float* __restrict__ ws,
                                               const float* __restrict__ wt, int N) {
    __shared__ float SM[64 * 97];
    __shared__ float sWgt[4 * 96];
    float* XS = SM;
    float* WS = SM + 64 * 33;
    float* PS = SM;

    int tid = threadIdx.x;
    int tm = tid & 31, tn = tid >> 5;
    int n0 = blockIdx.x * 64;
    int nn = min(64, N - n0);

    int r0 = tid >> 3, q0 = tid & 7;
    int r1 = (tid + 256) >> 3;
    const float* xp0 = x + (size_t)(n0 + ((r0 < nn) ? r0 : 0)) * INCH + q0 * 4;
    const float* xp1 = x + (size_t)(n0 + ((r1 < nn) ? r1 : 0)) * INCH + q0 * 4;
    float4 xr0[4], xr1[4];
    #pragma unroll
    for (int kt = 0; kt < 4; kt++) xr0[kt] = *(const float4*)(xp0 + kt * 32);
    #pragma unroll
    for (int kt = 0; kt < 4; kt++) xr1[kt] = *(const float4*)(xp1 + kt * 32);

    for (int i = tid; i < 192; i += 256) { sWgt[i] = ws[i]; sWgt[192 + i] = wt[i]; }

    float acc0[12], acc1[12];
    #pragma unroll
    for (int c = 0; c < 12; c++) { float b = b1[tn * 12 + c]; acc0[c] = b; acc1[c] = b; }

    #pragma unroll
    for (int kt = 0; kt < 4; kt++) {
        {
            float* d0 = &XS[r0 * 33 + q0 * 4];
            d0[0] = xr0[kt].x; d0[1] = xr0[kt].y; d0[2] = xr0[kt].z; d0[3] = xr0[kt].w;
            float* d1 = &XS[r1 * 33 + q0 * 4];
            d1[0] = xr1[kt].x; d1[1] = xr1[kt].y; d1[2] = xr1[kt].z; d1[3] = xr1[kt].w;
        }
        for (int l = tid; l < 768; l += 256) {
            int r = l / 24, q = l % 24;
            float4 v = *(const float4*)(g_W1t + (size_t)(kt * 32 + r) * FDH + q * 4);
            float* d = &WS[r * 96 + q * 4];
            d[0] = v.x; d[1] = v.y; d[2] = v.z; d[3] = v.w;
        }
        __syncthreads();
        #pragma unroll 4
        for (int k = 0; k < 32; k++) {
            float a0 = XS[tm * 33 + k];
            float a1 = XS[(tm + 32) * 33 + k];
            const float* wk = &WS[k * 96 + tn * 12];
            float4 b0 = *(const float4*)(wk);
            float4 b1v = *(const float4*)(wk + 4);
            float4 b2 = *(const float4*)(wk + 8);
            acc0[0] = fmaf(a0, b0.x, acc0[0]);  acc1[0] = fmaf(a1, b0.x, acc1[0]);
            acc0[1] = fmaf(a0, b0.y, acc0[1]);  acc1[1] = fmaf(a1, b0.y, acc1[1]);
            acc0[2] = fmaf(a0, b0.z, acc0[2]);  acc1[2] = fmaf(a1, b0.z, acc1[2]);
            acc0[3] = fmaf(a0, b0.w, acc0[3]);  acc1[3] = fmaf(a1, b0.w, acc1[3]);
            acc0[4] = fmaf(a0, b1v.x, acc0[4]); acc1[4] = fmaf(a1, b1v.x, acc1[4]);
            acc0[5] = fmaf(a0, b1v.y, acc0[5]); acc1[5] = fmaf(a1, b1v.y, acc1[5]);
            acc0[6] = fmaf(a0, b1v.z, acc0[6]); acc1[6] = fmaf(a1, b1v.z, acc1[6]);
            acc0[7] = fmaf(a0, b1v.w, acc0[7]); acc1[7] = fmaf(a1, b1v.w, acc1[7]);
            acc0[8] = fmaf(a0, b2.x, acc0[8]);  acc1[8] = fmaf(a1, b2.x, acc1[8]);
            acc0[9] = fmaf(a0, b2.y, acc0[9]);  acc1[9] = fmaf(a1, b2.y, acc1[9]);
            acc0[10] = fmaf(a0, b2.z, acc0[10]); acc1[10] = fmaf(a1, b2.z, acc1[10]);
            acc0[11] = fmaf(a0, b2.w, acc0[11]); acc1[11] = fmaf(a1, b2.w, acc1[11]);
        }
        __syncthreads();
    }

    #pragma unroll
    for (int c = 0; c < 12; c++) { acc0[c] = elu1(acc0[c]); acc1[c] = elu1(acc1[c]); }
    if (tm < nn) {
        float* xo = g_x + (size_t)(n0 + tm) * FDH + tn * 12;
        #pragma unroll
        for (int q = 0; q < 3; q++)
            *(float4*)(xo + q * 4) = make_float4(acc0[q*4], acc0[q*4+1], acc0[q*4+2], acc0[q*4+3]);
    }
    if (tm + 32 < nn) {
        float* xo = g_x + (size_t)(n0 + tm + 32) * FDH + tn * 12;
        #pragma unroll
        for (int q = 0; q < 3; q++)
            *(float4*)(xo + q * 4) = make_float4(acc1[q*4], acc1[q*4+1], acc1[q*4+2], acc1[q*4+3]);
    }
    {
        float* p0 = &PS[tm * 97 + tn * 12];
        float* p1 = &PS[(tm + 32) * 97 + tn * 12];
        #pragma unroll
        for (int c = 0; c < 12; c++) { p0[c] = acc0[c]; p1[c] = acc1[c]; }
    }
    __syncthreads();

    {
        int node = tid & 63;
        int widx = tid >> 6;
        if (node < nn) {
            const float* pv = &PS[node * 97];
            const float* wv = &sWgt[widx * 96];
            float s = 0.0f;
            #pragma unroll 8
            for (int j = 0; j < 96; j++) s = fmaf(pv[j], wv[j], s);
            ((float*)&g_proj[n0 + node])[widx] = s;
        }
        if (tid < nn) { g_degA[n0 + tid] = 0.0f; g_degB[n0 + tid] = 0.0f; }
    }
}

// ---------------- merged: edge transport+degree (CSR-slot writes)  ||  y-GEMM ----------------
__global__ void __launch_bounds__(256) k_edge_y(const int* __restrict__ row,
                                                const int* __restrict__ col,
                                                int layer, int E0, int nbE, int N) {
    if ((int)blockIdx.x < nbE) {
        int e = blockIdx.x * blockDim.x + threadIdx.x;
        if (e >= E0) return;
        float* deg = (layer == 0) ? g_degA : g_degB;
        int r = row[e], c = col[e];
        int pf = g_pos[e], pb = g_pos[e + E0];
        float4 pr = g_proj[r], pc = g_proj[c];
        float af = tanhf(pr.x + pc.y);
        float ab = tanhf(pc.x + pr.y);
        float af2 = af * af, ab2 = ab * ab;
        float invf = 1.0f / (1.0f + af2), invb = 1.0f / (1.0f + ab2);
        float cf = (1.0f - af2) * invf, sf = 2.0f * af * invf;
        float cb = (1.0f - ab2) * invb, sb = 2.0f * ab * invb;
        float t00 = cf * cb + sf * sb;
        float t01 = sf * cb - cf * sb;
        float wf = 1.0f / (1.0f + expf(-(pr.z + pc.w)));
        float wb = 1.0f / (1.0f + expf(-(pc.z + pr.w)));
        float w = wf * wb, w2 = w * w;
        g_ec[pf] = make_float4(t00,  t01, w2, __int_as_float(c));
        g_ec[pb] = make_float4(t00, -t01, w2, __int_as_float(r));
        atomicAdd(&deg[r], w2);
        atomicAdd(&deg[c], w2);
        return;
    }

    __shared__ float MS[192 * 33];
    __shared__ float sB[HID * HID];
    __shared__ float sWl[9];
    int tid = threadIdx.x;
    for (int i = tid; i < HID * HID; i += 256) sB[i] = g_WrT[layer * HID * HID + i];
    if (tid < 9) sWl[tid] = g_Wl[layer * 9 + tid];
    __syncthreads();

    int n0 = ((int)blockIdx.x - nbE) * 64;
    int nn = min(64, N - n0);
    if (nn <= 0) return;
    int tot = nn * FDH;
    for (int idx = tid; idx < tot; idx += 256) {
        int m = idx >> 5, h = idx & 31;
        int nl = m / 3, f = m % 3;
        const float* xr = g_x + (size_t)(n0 + nl) * FDH + h;
        MS[m * 33 + h] = sWl[f * 3 + 0] * xr[0] + sWl[f * 3 + 1] * xr[32]
                       + sWl[f * 3 + 2] * xr[64];
    }
    __syncthreads();

    int tm = tid & 31, tn = tid >> 5;
    float acc[6][4];
    #pragma unroll
    for (int j = 0; j < 6; j++)
        #pragma unroll
        for (int q = 0; q < 4; q++) acc[j][q] = 0.0f;

    #pragma unroll 4
    for (int k = 0; k < HID; k++) {
        float4 bv = *(const float4*)&sB[k * HID + tn * 4];
        #pragma unroll
        for (int j = 0; j < 6; j++) {
            float a = MS[(tm + j * 32) * 33 + k];
            acc[j][0] = fmaf(a, bv.x, acc[j][0]);
            acc[j][1] = fmaf(a, bv.y, acc[j][1]);
            acc[j][2] = fmaf(a, bv.z, acc[j][2]);
            acc[j][3] = fmaf(a, bv.w, acc[j][3]);
        }
    }
    #pragma unroll
    for (int j = 0; j < 6; j++) {
        int m = tm + j * 32;
        int nl = m / 3, f = m % 3;
        if (nl < nn) {
            float4* yo = (float4*)(g_y + (size_t)(n0 + nl) * FDH + f * 32 + tn * 4);
            *yo = make_float4(acc[j][0], acc[j][1], acc[j][2], acc[j][3]);
        }
    }
}

// ---------------- gather: agg + update x; warp per node; 4-deep pipeline ----------------
#define GACC(EC, Y0, Y1, Y2, DC)                                     \
    { float ic = ((DC) > 0.0f) ? rsqrtf(fmaxf((DC), 1e-30f)) : 0.0f; \
      float cc = (EC).z * ir * ic;                                   \
      A0 = fmaf(cc, fmaf((EC).x, (Y0),  (EC).y * (Y1)), A0);         \
      A1 = fmaf(cc, fmaf((EC).x, (Y1), -(EC).y * (Y0)), A1);         \
      A2 = fmaf(cc, (Y2), A2); }
#define GLOAD(EC, Y0, Y1, Y2, DC, IDX)                               \
    { (EC) = ep[IDX];                                                \
      int ci_ = __float_as_int((EC).w);                              \
      const float* yc = g_y + (size_t)ci_ * FDH;                     \
      (Y0) = yc[lane]; (Y1) = yc[32 + lane]; (Y2) = yc[64 + lane];   \
      (DC) = deg[ci_]; }

__global__ void __launch_bounds__(256) k_gather(int layer,
                                                const float* __restrict__ ws,
                                                const float* __restrict__ wt, int N) {
    int tid  = threadIdx.x;
    int n    = (blockIdx.x * blockDim.x + tid) >> 5;
    int lane = tid & 31;
    if (n >= N) return;
    const float* deg = (layer == 0) ? g_degA : g_degB;
    const float* coeff = g_coeff + layer * 3;

    float dn = deg[n];
    float diag = (dn > 0.0f) ? 1.0f : 0.0f;
    float ir = (dn > 0.0f) ? rsqrtf(fmaxf(dn, 1e-30f)) : 0.0f;
    int beg = g_ofs[n], cnt = g_num[n];
    const float4* ep = g_ec + beg;
    float A0 = 0.0f, A1 = 0.0f, A2 = 0.0f;

    float4 e0, e1, e2, e3;
    float y00, y01, y02, y10, y11, y12, y20, y21, y22, y30, y31, y32;
    float d0, d1, d2, d3;
    if (cnt > 0) GLOAD(e0, y00, y01, y02, d0, 0);
    if (cnt > 1) GLOAD(e1, y10, y11, y12, d1, 1);
    if (cnt > 2) GLOAD(e2, y20, y21, y22, d2, 2);
    if (cnt > 3) GLOAD(e3, y30, y31, y32, d3, 3);

    int i = 0;
    while (i + 4 <= cnt) {
        GACC(e0, y00, y01, y02, d0); if (i + 4 < cnt) GLOAD(e0, y00, y01, y02, d0, i + 4);
        GACC(e1, y10, y11, y12, d1); if (i + 5 < cnt) GLOAD(e1, y10, y11, y12, d1, i + 5);
        GACC(e2, y20, y21, y22, d2); if (i + 6 < cnt) GLOAD(e2, y20, y21, y22, d2, i + 6);
        GACC(e3, y30, y31, y32, d3); if (i + 7 < cnt) GLOAD(e3, y30, y31, y32, d3, i + 7);
        i += 4;
    }
    int rem = cnt - i;
    if (rem > 0) GACC(e0, y00, y01, y02, d0);
    if (rem > 1) GACC(e1, y10, y11, y12, d1);
    if (rem > 2) GACC(e2, y20, y21, y22, d2);

    const float* yn = g_y + (size_t)n * FDH;
    float* xr = g_x + (size_t)n * FDH;
    float x0 = coeff[0] * xr[lane]      - elu1(diag * yn[lane]      - A0);
    float x1 = coeff[1] * xr[32 + lane] - elu1(diag * yn[32 + lane] - A1);
    float x2 = coeff[2] * xr[64 + lane] - elu1(diag * yn[64 + lane] - A2);
    xr[lane] = x0; xr[32 + lane] = x1; xr[64 + lane] = x2;
    if (layer == 0) do_proj(n, lane, x0, x1, x2, ws, wt);
}

// ---------------- out: final GEMM x[N,96] @ W2t[96,32] + b2; 64 nodes/block ----------------
__global__ void __launch_bounds__(256) k_out(const float* __restrict__ b2,
                                             float* __restrict__ out, int N) {
    __shared__ float XS[64 * 97];
    __shared__ float sB[FDH * OUTCH];
    int tid = threadIdx.x;
    for (int i = tid; i < FDH * OUTCH; i += 256) sB[i] = g_W2t[i];

    int n0 = blockIdx.x * 64;
    int nn = min(64, N - n0);
    for (int idx = tid; idx < nn * 24; idx += 256) {
        int nl = idx / 24, q = idx % 24;
        float4 v = *(const float4*)(g_x + (size_t)(n0 + nl) * FDH + q * 4);
        float* d = &XS[nl * 97 + q * 4];
        d[0] = v.x; d[1] = v.y; d[2] = v.z; d[3] = v.w;
    }
    __syncthreads();

    int tm = tid & 31, tn = tid >> 5;
    float4 bias = *(const float4*)(b2 + tn * 4);
    float acc0[4] = {bias.x, bias.y, bias.z, bias.w};
    float acc1[4] = {bias.x, bias.y, bias.z, bias.w};
    #pragma unroll 4
    for (int k = 0; k < FDH; k++) {
        float4 bv = *(const float4*)&sB[k * OUTCH + tn * 4];
        float a0 = XS[tm * 97 + k];
        float a1 = XS[(tm + 32) * 97 + k];
        acc0[0] = fmaf(a0, bv.x, acc0[0]); acc0[1] = fmaf(a0, bv.y, acc0[1]);
        acc0[2] = fmaf(a0, bv.z, acc0[2]); acc0[3] = fmaf(a0, bv.w, acc0[3]);
        acc1[0] = fmaf(a1, bv.x, acc1[0]); acc1[1] = fmaf(a1, bv.y, acc1[1]);
        acc1[2] = fmaf(a1, bv.z, acc1[2]); acc1[3] = fmaf(a1, bv.w, acc1[3]);
    }
    if (tm < nn)
        *(float4*)(out + (size_t)(n0 + tm) * OUTCH + tn * 4) =
            make_float4(acc0[0], acc0[1], acc0[2], acc0[3]);
    if (tm + 32 < nn)
        *(float4*)(out + (size_t)(n0 + tm + 32) * OUTCH + tn * 4) =
            make_float4(acc1[0], acc1[1], acc1[2], acc1[3]);
}

// ---------------- launch ----------------
extern "C" void kernel_launch(void* const* d_in, const int* in_sizes, int n_in,
                              void* d_out, int out_size)
{
    const float* x      = (const float*)d_in[0];
    const int*   ei     = (const int*)  d_in[1];
    const float* W1     = (const float*)d_in[2];
    const float* b1     = (const float*)d_in[3];
    const float* W2     = (const float*)d_in[4];
    const float* b2     = (const float*)d_in[5];
    const float* Wleft  = (const float*)d_in[6];
    const float* Wright = (const float*)d_in[7];
    const float* eps    = (const float*)d_in[8];
    const float* Wsheaf = (const float*)d_in[9];
    const float* Wwt    = (const float*)d_in[10];
    float* out = (float*)d_out;

    int N  = in_sizes[0] / INCH;
    int E  = in_sizes[1] / 2;
    int E0 = E / 2;
    const int* row = ei;
    const int* col = ei + E;

    int nbE  = (E0 + 255) / 256;
    int nb64 = (N + 63) / 64;
    int nbH  = (E / 4 + 255) / 256;

    k_init<<<(N + 255) / 256, 256>>>(W1, W2, N);                       // 1
    k_spec_hist<<<2 + nbH, 256>>>(Wleft, Wright, eps, row, E);         // 2
    k_assign<<<(N + 255) / 256, 256>>>(N);                             // 3
    k_lin1G<<<nb64, 256>>>(x, b1, Wsheaf + 192, Wwt, N);               // 4  <- profiled
    k_scatter<<<(E + 255) / 256, 256>>>(row, E);                       // 5
    // layer 0
    k_edge_y<<<nbE + nb64, 256>>>(row, col, 0, E0, nbE, N);            // 6
    k_gather<<<(N * 32 + 255) / 256, 256>>>(0, Wsheaf + 576 + 192, Wwt + 192, N); // 7
    // layer 1
    k_edge_y<<<nbE + nb64, 256>>>(row, col, 1, E0, nbE, N);            // 8
    k_gather<<<(N * 32 + 255) / 256, 256>>>(1, Wsheaf, Wwt, N);        // 9

    k_out<<<nb64, 256>>>(b2, out, N);                                  // 10
}